// round 7
// baseline (speedup 1.0000x reference)
#include <cuda_runtime.h>
#include <math.h>

#define BB 16
#define TT 2048
#define DD 2048
#define CC 100

#define ALPHA 0.0005f
#define MARGIN 100.0f
#define EPS_C 1e-7f

#define FEAT_BLOCKS 1024   // 16 tchunks x 2 dchunks x 32 (tensor,b)
#define BTC_BLOCKS  512    // 32 tchunks(64t) x 16 b
#define TOTAL_BLOCKS (FEAT_BLOCKS + BTC_BLOCKS)

// ---------------- scratch (device globals; zero-init at load) ----------------
// Invariant: zero at kernel_launch entry; tail (in last block) re-zeros all.
__device__ float g_colsum[2][BB * DD];  // [tensor][b*D + d] column sums over t
__device__ float g_sq[BB * CC];         // sum_t (sup - pmask)^2 per (b,c)
__device__ float g_pos[BB * CC];        // sum_t pmask per (b,c)
__device__ float g_st[1];               // sum (cas_s - cas_t)^2
__device__ unsigned int g_done;         // completed-block counter

// block reduce over 256 threads
__device__ __forceinline__ float block_reduce_256(float v, float* red) {
    int tid = threadIdx.x;
    red[tid] = v;
    __syncthreads();
    for (int s = 128; s > 0; s >>= 1) {
        if (tid < s) red[tid] += red[tid + s];
        __syncthreads();
    }
    float r = red[0];
    __syncthreads();
    return r;
}

__global__ __launch_bounds__(256) void main_kernel(
    const float* __restrict__ fa, const float* __restrict__ fb,
    const float* __restrict__ gt, const float* __restrict__ sup,
    const float* __restrict__ cas_s, const float* __restrict__ cas_t,
    const float* __restrict__ score_act, const float* __restrict__ score_bkg,
    const float* __restrict__ label, float* __restrict__ out) {
    const int bz = blockIdx.x;
    const int tid = threadIdx.x;
    __shared__ float sh[256];
    __shared__ float n2s[2 * BB];
    __shared__ float lsum[BB];
    __shared__ unsigned int s_rank;

    if (bz < FEAT_BLOCKS) {
        // ---- feat column sums: tile = [128 t x 1024 d] ----
        const int tch = bz & 15;
        const int dch = (bz >> 4) & 1;
        const int z = bz >> 5;            // 0..31
        const int tensor = z >> 4;
        const int b = z & 15;
        const float* __restrict__ f = tensor ? fb : fa;

        const int d0 = dch * 1024 + (tid << 2);
        const size_t base = (size_t)b * TT * DD + (size_t)tch * 128 * DD + d0;
        const float4* __restrict__ p = (const float4*)(f + base);

        float4 acc = make_float4(0.f, 0.f, 0.f, 0.f);
#pragma unroll 16
        for (int t = 0; t < 128; t++) {
            float4 v = __ldcs(p + (size_t)t * (DD / 4));
            acc.x += v.x; acc.y += v.y; acc.z += v.z; acc.w += v.w;
        }
        float* cs = &g_colsum[tensor][b * DD + d0];
        atomicAdd(cs + 0, acc.x);
        atomicAdd(cs + 1, acc.y);
        atomicAdd(cs + 2, acc.z);
        atomicAdd(cs + 3, acc.w);
    } else {
        // ---- [B,T,C] streams: sup / pos / st ----
        const int i = bz - FEAT_BLOCKS;   // 0..511
        const int b = i >> 5;
        const int tci = i & 31;
        const int half = tid >> 7;        // 0 or 1
        const int c = tid & 127;
        const int t0 = tci * 64 + half * 32;

        float sq = 0.f, pos = 0.f, st = 0.f;
        if (c < CC) {
            size_t base = (size_t)b * TT * CC + (size_t)t0 * CC + c;
#pragma unroll 4
            for (int t = 0; t < 32; t++) {
                size_t o = base + (size_t)t * CC;
                float g = __ldcs(gt + o);
                float s = __ldcs(sup + o);
                float x = __ldcs(cas_s + o);
                float y = __ldcs(cas_t + o);
                float pm = (g > 0.5f) ? 1.f : 0.f;
                float d = s - pm;
                sq += d * d;
                pos += pm;
                float e = x - y;
                st += e * e;
            }
            atomicAdd(&g_sq[b * CC + c], sq);
            atomicAdd(&g_pos[b * CC + c], pos);
        }
        sh[tid] = st;
        __syncthreads();
        for (int s = 128; s > 0; s >>= 1) {
            if (tid < s) sh[tid] += sh[tid + s];
            __syncthreads();
        }
        if (tid == 0) atomicAdd(g_st, sh[0]);
    }

    // ---------------- completion handshake ----------------
    __threadfence();
    __syncthreads();
    if (tid == 0) s_rank = atomicAdd(&g_done, 1u);
    __syncthreads();
    if (s_rank != TOTAL_BLOCKS - 1) return;

    // ======== TAIL: executed by the last-finishing block only ========
    if (tid == 0) g_done = 0;

    // ---- per-(tensor,b) squared norms of mean features; zero colsum ----
    // 8 warps; warp w handles rows w, w+8, w+16, w+24 (32 rows total).
    {
        const int w = tid >> 5;
        const int lane = tid & 31;
        for (int k = w; k < 2 * BB; k += 8) {
            float* cs = &g_colsum[k >> 4][(k & 15) * DD];
            float s = 0.f;
#pragma unroll 8
            for (int i = lane; i < DD; i += 32) {
                float v = cs[i] * (1.0f / TT);
                s += v * v;
                cs[i] = 0.f;
            }
#pragma unroll
            for (int o = 16; o > 0; o >>= 1)
                s += __shfl_xor_sync(0xFFFFFFFFu, s, o);
            if (lane == 0) n2s[k] = s;
        }
    }

    // ---- label row-sums (shared atomics) ----
    if (tid < BB) lsum[tid] = 0.f;
    __syncthreads();
    for (int i = tid; i < BB * CC; i += 256)
        atomicAdd(&lsum[i / CC], label[i]);
    __syncthreads();

    // ---- BCE terms over [B,C] ----
    float acc_cls = 0.f, acc_be = 0.f;
    const float tb = 1.0f / CC;
    for (int i = tid; i < BB * CC; i += 256) {
        float p = score_act[i];
        p = fminf(fmaxf(p, EPS_C), 1.0f - EPS_C);
        float t = label[i] / lsum[i / CC];
        acc_cls += t * logf(p) + (1.0f - t) * log1pf(-p);

        float q = score_bkg[i];
        q = fminf(fmaxf(q, EPS_C), 1.0f - EPS_C);
        acc_be += tb * logf(q) + (1.0f - tb) * log1pf(-q);
    }
    float sum_cls = block_reduce_256(acc_cls, sh);
    float sum_be  = block_reduce_256(acc_be, sh);

    // ---- loss_sup; zero g_sq/g_pos after reading ----
    float acc_sup = 0.f, acc_cnt = 0.f;
    for (int i = tid; i < BB * CC; i += 256) {
        float pv = g_pos[i];
        float qv = g_sq[i];
        if (pv > 0.f) {
            acc_sup += sqrtf(qv);
            acc_cnt += 1.f;
        }
        g_pos[i] = 0.f;
        g_sq[i] = 0.f;
    }
    float sum_sup = block_reduce_256(acc_sup, sh);
    float sum_cnt = block_reduce_256(acc_cnt, sh);

    // ---- loss_um from n2s (16 lanes active) ----
    float um_part = 0.f;
    if (tid < BB) {
        float an = sqrtf(n2s[tid]);
        float bn = sqrtf(n2s[BB + tid]);
        float la = fmaxf(MARGIN - an, 0.f);
        float v = la + bn;
        um_part = v * v;
    }
    float sum_um = block_reduce_256(um_part, sh);

    if (tid == 0) {
        float st_sum = g_st[0];
        g_st[0] = 0.f;

        float loss_cls = -sum_cls / (float)(BB * CC);
        float loss_be  = -sum_be  / (float)(BB * CC);
        float loss_um  = sum_um / (float)BB;
        float loss_sup = sum_sup / fmaxf(sum_cnt, 1.0f);
        float loss_st  = st_sum / (float)(BB * TT * CC);

        float total = loss_cls + ALPHA * loss_um + loss_be + loss_sup + loss_st;
        out[0] = total;
        out[1] = loss_cls;
        out[2] = loss_be;
        out[3] = loss_um;
        out[4] = loss_sup;
        out[5] = loss_st;
    }
}

// ---------------- launch ----------------
extern "C" void kernel_launch(void* const* d_in, const int* in_sizes, int n_in,
                              void* d_out, int out_size) {
    const float* score_act = (const float*)d_in[0];
    const float* score_bkg = (const float*)d_in[1];
    const float* feat_act  = (const float*)d_in[2];
    const float* feat_bkg  = (const float*)d_in[3];
    const float* label     = (const float*)d_in[4];
    const float* gt        = (const float*)d_in[5];
    const float* sup_cas   = (const float*)d_in[6];
    const float* cas_s     = (const float*)d_in[7];
    const float* cas_t     = (const float*)d_in[8];

    main_kernel<<<TOTAL_BLOCKS, 256>>>(
        feat_act, feat_bkg, gt, sup_cas, cas_s, cas_t,
        score_act, score_bkg, label, (float*)d_out);
}

// round 9
// speedup vs baseline: 1.1474x; 1.1474x over previous
#include <cuda_runtime.h>
#include <math.h>

#define BB 16
#define TT 2048
#define DD 2048
#define CC 100

#define ALPHA 0.0005f
#define MARGIN 100.0f
#define EPS_C 1e-7f

#define FEAT_BLOCKS 1024   // 16 tchunks x 2 dchunks x 32 (tensor,b)
#define BTC_BLOCKS  512    // 32 tchunks(64t) x 16 b
#define TOTAL_BLOCKS (FEAT_BLOCKS + BTC_BLOCKS)

// ---------------- scratch (device globals; zero-init at load) ----------------
// Invariant: zero at kernel_launch entry; tail_kernel re-zeros after reading.
__device__ float g_colsum[2][BB * DD];  // [tensor][b*D + d] column sums over t
__device__ float g_sq[BB * CC];         // sum_t (sup - pmask)^2 per (b,c)
__device__ float g_pos[BB * CC];        // sum_t pmask per (b,c)
__device__ float g_st[1];               // sum (cas_s - cas_t)^2
__device__ float g_n2[2 * BB];          // squared norms of mean features
__device__ unsigned int g_done;         // tail completion counter

// ---------------- fused streaming kernel (R5-proven, untouched) --------------
__global__ __launch_bounds__(256) void main_kernel(
    const float* __restrict__ fa, const float* __restrict__ fb,
    const float* __restrict__ gt, const float* __restrict__ sup,
    const float* __restrict__ cas_s, const float* __restrict__ cas_t) {
    const int bz = blockIdx.x;
    const int tid = threadIdx.x;

    if (bz < FEAT_BLOCKS) {
        // ---- feat column sums: tile = [128 t x 1024 d] ----
        const int tch = bz & 15;
        const int dch = (bz >> 4) & 1;
        const int z = bz >> 5;            // 0..31
        const int tensor = z >> 4;
        const int b = z & 15;
        const float* __restrict__ f = tensor ? fb : fa;

        const int d0 = dch * 1024 + (tid << 2);
        const size_t base = (size_t)b * TT * DD + (size_t)tch * 128 * DD + d0;
        const float4* __restrict__ p = (const float4*)(f + base);

        float4 acc = make_float4(0.f, 0.f, 0.f, 0.f);
#pragma unroll 16
        for (int t = 0; t < 128; t++) {
            float4 v = __ldcs(p + (size_t)t * (DD / 4));
            acc.x += v.x; acc.y += v.y; acc.z += v.z; acc.w += v.w;
        }
        float* cs = &g_colsum[tensor][b * DD + d0];
        atomicAdd(cs + 0, acc.x);
        atomicAdd(cs + 1, acc.y);
        atomicAdd(cs + 2, acc.z);
        atomicAdd(cs + 3, acc.w);
    } else {
        // ---- [B,T,C] streams: sup / pos / st ----
        const int i = bz - FEAT_BLOCKS;   // 0..511
        const int b = i >> 5;
        const int tci = i & 31;
        const int half = tid >> 7;        // 0 or 1
        const int c = tid & 127;
        const int t0 = tci * 64 + half * 32;

        float sq = 0.f, pos = 0.f, st = 0.f;
        if (c < CC) {
            size_t base = (size_t)b * TT * CC + (size_t)t0 * CC + c;
#pragma unroll 4
            for (int t = 0; t < 32; t++) {
                size_t o = base + (size_t)t * CC;
                float g = __ldcs(gt + o);
                float s = __ldcs(sup + o);
                float x = __ldcs(cas_s + o);
                float y = __ldcs(cas_t + o);
                float pm = (g > 0.5f) ? 1.f : 0.f;
                float d = s - pm;
                sq += d * d;
                pos += pm;
                float e = x - y;
                st += e * e;
            }
            atomicAdd(&g_sq[b * CC + c], sq);
            atomicAdd(&g_pos[b * CC + c], pos);
        }
        __shared__ float sh[256];
        sh[tid] = st;
        __syncthreads();
        for (int s = 128; s > 0; s >>= 1) {
            if (tid < s) sh[tid] += sh[tid + s];
            __syncthreads();
        }
        if (tid == 0) atomicAdd(g_st, sh[0]);
    }
}

// ---------------- tail: 32 parallel norm blocks; last block assembles -------
__device__ __forceinline__ float block_reduce_256(float v, float* red) {
    int tid = threadIdx.x;
    red[tid] = v;
    __syncthreads();
    for (int s = 128; s > 0; s >>= 1) {
        if (tid < s) red[tid] += red[tid + s];
        __syncthreads();
    }
    float r = red[0];
    __syncthreads();
    return r;
}

__global__ __launch_bounds__(256) void tail_kernel(
    const float* __restrict__ score_act, const float* __restrict__ score_bkg,
    const float* __restrict__ label, float* __restrict__ out) {
    const int tid = threadIdx.x;
    const int k = blockIdx.x;           // 0..31 -> (tensor,b)
    __shared__ float red[256];
    __shared__ float lsum[BB];
    __shared__ unsigned int s_rank;

    // ---- parallel: squared norm of mean feature for row k; zero colsum ----
    {
        float* cs = &g_colsum[k >> 4][(k & 15) * DD];
        float s = 0.f;
#pragma unroll 4
        for (int i = tid; i < DD; i += 256) {
            float v = cs[i] * (1.0f / TT);
            s += v * v;
            cs[i] = 0.f;
        }
        s = block_reduce_256(s, red);
        if (tid == 0) g_n2[k] = s;
    }

    // ---- handshake: last-finishing block runs final assembly ----
    __threadfence();
    __syncthreads();
    if (tid == 0) s_rank = atomicAdd(&g_done, 1u);
    __syncthreads();
    if (s_rank != 2 * BB - 1) return;

    if (tid == 0) g_done = 0;

    // ---- label row-sums (shared atomics) ----
    if (tid < BB) lsum[tid] = 0.f;
    __syncthreads();
    for (int i = tid; i < BB * CC; i += 256)
        atomicAdd(&lsum[i / CC], label[i]);
    __syncthreads();

    // ---- BCE terms over [B,C] ----
    float acc_cls = 0.f, acc_be = 0.f;
    const float tb = 1.0f / CC;
    for (int i = tid; i < BB * CC; i += 256) {
        float p = score_act[i];
        p = fminf(fmaxf(p, EPS_C), 1.0f - EPS_C);
        float t = label[i] / lsum[i / CC];
        acc_cls += t * logf(p) + (1.0f - t) * log1pf(-p);

        float q = score_bkg[i];
        q = fminf(fmaxf(q, EPS_C), 1.0f - EPS_C);
        acc_be += tb * logf(q) + (1.0f - tb) * log1pf(-q);
    }
    float sum_cls = block_reduce_256(acc_cls, red);
    float sum_be  = block_reduce_256(acc_be, red);

    // ---- loss_sup; zero g_sq/g_pos after reading ----
    float acc_sup = 0.f, acc_cnt = 0.f;
    for (int i = tid; i < BB * CC; i += 256) {
        float pv = g_pos[i];
        float qv = g_sq[i];
        if (pv > 0.f) {
            acc_sup += sqrtf(qv);
            acc_cnt += 1.f;
        }
        g_pos[i] = 0.f;
        g_sq[i] = 0.f;
    }
    float sum_sup = block_reduce_256(acc_sup, red);
    float sum_cnt = block_reduce_256(acc_cnt, red);

    // ---- loss_um from g_n2 (16 lanes active; written before fence) ----
    float um_part = 0.f;
    if (tid < BB) {
        float an = sqrtf(g_n2[tid]);
        float bn = sqrtf(g_n2[BB + tid]);
        float la = fmaxf(MARGIN - an, 0.f);
        float v = la + bn;
        um_part = v * v;
    }
    float sum_um = block_reduce_256(um_part, red);

    if (tid == 0) {
        float st_sum = g_st[0];
        g_st[0] = 0.f;

        float loss_cls = -sum_cls / (float)(BB * CC);
        float loss_be  = -sum_be  / (float)(BB * CC);
        float loss_um  = sum_um / (float)BB;
        float loss_sup = sum_sup / fmaxf(sum_cnt, 1.0f);
        float loss_st  = st_sum / (float)(BB * TT * CC);

        float total = loss_cls + ALPHA * loss_um + loss_be + loss_sup + loss_st;
        out[0] = total;
        out[1] = loss_cls;
        out[2] = loss_be;
        out[3] = loss_um;
        out[4] = loss_sup;
        out[5] = loss_st;
    }
}

// ---------------- launch ----------------
extern "C" void kernel_launch(void* const* d_in, const int* in_sizes, int n_in,
                              void* d_out, int out_size) {
    const float* score_act = (const float*)d_in[0];
    const float* score_bkg = (const float*)d_in[1];
    const float* feat_act  = (const float*)d_in[2];
    const float* feat_bkg  = (const float*)d_in[3];
    const float* label     = (const float*)d_in[4];
    const float* gt        = (const float*)d_in[5];
    const float* sup_cas   = (const float*)d_in[6];
    const float* cas_s     = (const float*)d_in[7];
    const float* cas_t     = (const float*)d_in[8];

    main_kernel<<<TOTAL_BLOCKS, 256>>>(feat_act, feat_bkg, gt, sup_cas, cas_s, cas_t);
    tail_kernel<<<2 * BB, 256>>>(score_act, score_bkg, label, (float*)d_out);
}

// round 10
// speedup vs baseline: 1.1889x; 1.0362x over previous
#include <cuda_runtime.h>
#include <math.h>

#define BB 16
#define TT 2048
#define DD 2048
#define CC 100

#define ALPHA 0.0005f
#define MARGIN 100.0f
#define EPS_C 1e-7f

#define FEAT_DCHUNK 64                        // floats per d-strip
#define FEAT_NDCH (DD / FEAT_DCHUNK)          // 32
#define FEAT_BLOCKS (2 * BB * FEAT_NDCH)      // 1024
#define BTC_BLOCKS 512                        // 32 tchunks(64t) x 16 b
#define TOTAL_BLOCKS (FEAT_BLOCKS + BTC_BLOCKS)

// ---------------- scratch (device globals; zero-init at load) ----------------
// Invariant: zero at kernel_launch entry; final_kernel re-zeros after reading.
__device__ float g_n2[2 * BB];          // squared norms of mean features (atomic-accum)
__device__ float g_sq[BB * CC];         // sum_t (sup - pmask)^2 per (b,c)
__device__ float g_pos[BB * CC];        // sum_t pmask per (b,c)
__device__ float g_st[1];               // sum (cas_s - cas_t)^2

// ---------------- fused streaming kernel ----------------
__global__ __launch_bounds__(256) void main_kernel(
    const float* __restrict__ fa, const float* __restrict__ fb,
    const float* __restrict__ gt, const float* __restrict__ sup,
    const float* __restrict__ cas_s, const float* __restrict__ cas_t) {
    const int bz = blockIdx.x;
    const int tid = threadIdx.x;
    __shared__ float shbuf[16 * 16 * 4];   // feat: 16x16 float4; btc: 256 floats

    if (bz < FEAT_BLOCKS) {
        // ---- feat: block owns (tensor, b, 64-float d-strip) across ALL t ----
        const int dch = bz & (FEAT_NDCH - 1);
        const int z = bz >> 5;            // 0..31
        const int tensor = z >> 4;
        const int b = z & 15;
        const float* __restrict__ f = tensor ? fb : fa;

        const int lane16 = tid & 15;      // d-lane (float4)
        const int rg = tid >> 4;          // row-group 0..15
        const int d0 = dch * FEAT_DCHUNK + lane16 * 4;
        const float4* __restrict__ p =
            (const float4*)(f + (size_t)b * TT * DD + (size_t)rg * DD + d0);

        float4 acc = make_float4(0.f, 0.f, 0.f, 0.f);
#pragma unroll 8
        for (int t = 0; t < TT / 16; t++) {           // 128 iterations
            float4 v = __ldcs(p + (size_t)t * (16 * DD / 4));
            acc.x += v.x; acc.y += v.y; acc.z += v.z; acc.w += v.w;
        }

        // combine 16 row-group partials per d-column in shared
        float4* sh4 = (float4*)shbuf;     // [16 rg][16 lane]
        sh4[rg * 16 + lane16] = acc;
        __syncthreads();

        float partial = 0.f;
        if (tid < 16) {
            float4 c = sh4[tid];
#pragma unroll
            for (int r = 1; r < 16; r++) {
                float4 v = sh4[r * 16 + tid];
                c.x += v.x; c.y += v.y; c.z += v.z; c.w += v.w;
            }
            const float invT = 1.0f / TT;
            float x = c.x * invT, y = c.y * invT, zz = c.z * invT, w = c.w * invT;
            partial = x * x + y * y + zz * zz + w * w;
        }
        if (tid < 32) {
#pragma unroll
            for (int o = 16; o > 0; o >>= 1)
                partial += __shfl_xor_sync(0xFFFFFFFFu, partial, o);
            if (tid == 0) atomicAdd(&g_n2[z], partial);
        }
    } else {
        // ---- [B,T,C] streams: sup / pos / st ----
        const int i = bz - FEAT_BLOCKS;   // 0..511
        const int b = i >> 5;
        const int tci = i & 31;
        const int half = tid >> 7;        // 0 or 1
        const int c = tid & 127;
        const int t0 = tci * 64 + half * 32;

        float sq = 0.f, pos = 0.f, st = 0.f;
        if (c < CC) {
            size_t base = (size_t)b * TT * CC + (size_t)t0 * CC + c;
#pragma unroll 4
            for (int t = 0; t < 32; t++) {
                size_t o = base + (size_t)t * CC;
                float g = __ldcs(gt + o);
                float s = __ldcs(sup + o);
                float x = __ldcs(cas_s + o);
                float y = __ldcs(cas_t + o);
                float pm = (g > 0.5f) ? 1.f : 0.f;
                float d = s - pm;
                sq += d * d;
                pos += pm;
                float e = x - y;
                st += e * e;
            }
            atomicAdd(&g_sq[b * CC + c], sq);
            atomicAdd(&g_pos[b * CC + c], pos);
        }
        float* sh = shbuf;
        sh[tid] = st;
        __syncthreads();
        for (int s = 128; s > 0; s >>= 1) {
            if (tid < s) sh[tid] += sh[tid + s];
            __syncthreads();
        }
        if (tid == 0) atomicAdd(g_st, sh[0]);
    }
}

// ---------------- final: one small block, no colsum walk --------------------
__device__ __forceinline__ float block_reduce_256(float v, float* red) {
    int tid = threadIdx.x;
    red[tid] = v;
    __syncthreads();
    for (int s = 128; s > 0; s >>= 1) {
        if (tid < s) red[tid] += red[tid + s];
        __syncthreads();
    }
    float r = red[0];
    __syncthreads();
    return r;
}

__global__ __launch_bounds__(256) void final_kernel(
    const float* __restrict__ score_act, const float* __restrict__ score_bkg,
    const float* __restrict__ label, float* __restrict__ out) {
    const int tid = threadIdx.x;
    __shared__ float red[256];
    __shared__ float lsum[BB];

    // ---- label row-sums (shared atomics) ----
    if (tid < BB) lsum[tid] = 0.f;
    __syncthreads();
    for (int i = tid; i < BB * CC; i += 256)
        atomicAdd(&lsum[i / CC], label[i]);
    __syncthreads();

    // ---- BCE terms over [B,C] ----
    float acc_cls = 0.f, acc_be = 0.f;
    const float tb = 1.0f / CC;
    for (int i = tid; i < BB * CC; i += 256) {
        float p = score_act[i];
        p = fminf(fmaxf(p, EPS_C), 1.0f - EPS_C);
        float t = label[i] / lsum[i / CC];
        acc_cls += t * logf(p) + (1.0f - t) * log1pf(-p);

        float q = score_bkg[i];
        q = fminf(fmaxf(q, EPS_C), 1.0f - EPS_C);
        acc_be += tb * logf(q) + (1.0f - tb) * log1pf(-q);
    }
    float sum_cls = block_reduce_256(acc_cls, red);
    float sum_be  = block_reduce_256(acc_be, red);

    // ---- loss_sup; zero g_sq/g_pos after reading ----
    float acc_sup = 0.f, acc_cnt = 0.f;
    for (int i = tid; i < BB * CC; i += 256) {
        float pv = g_pos[i];
        float qv = g_sq[i];
        if (pv > 0.f) {
            acc_sup += sqrtf(qv);
            acc_cnt += 1.f;
        }
        g_pos[i] = 0.f;
        g_sq[i] = 0.f;
    }
    float sum_sup = block_reduce_256(acc_sup, red);
    float sum_cnt = block_reduce_256(acc_cnt, red);

    // ---- loss_um from g_n2 (16 lanes active); zero g_n2 after read ----
    float um_part = 0.f;
    if (tid < BB) {
        float an = sqrtf(g_n2[tid]);
        float bn = sqrtf(g_n2[BB + tid]);
        float la = fmaxf(MARGIN - an, 0.f);
        float v = la + bn;
        um_part = v * v;
    }
    __syncthreads();
    if (tid < 2 * BB) g_n2[tid] = 0.f;
    float sum_um = block_reduce_256(um_part, red);

    if (tid == 0) {
        float st_sum = g_st[0];
        g_st[0] = 0.f;

        float loss_cls = -sum_cls / (float)(BB * CC);
        float loss_be  = -sum_be  / (float)(BB * CC);
        float loss_um  = sum_um / (float)BB;
        float loss_sup = sum_sup / fmaxf(sum_cnt, 1.0f);
        float loss_st  = st_sum / (float)(BB * TT * CC);

        float total = loss_cls + ALPHA * loss_um + loss_be + loss_sup + loss_st;
        out[0] = total;
        out[1] = loss_cls;
        out[2] = loss_be;
        out[3] = loss_um;
        out[4] = loss_sup;
        out[5] = loss_st;
    }
}

// ---------------- launch ----------------
extern "C" void kernel_launch(void* const* d_in, const int* in_sizes, int n_in,
                              void* d_out, int out_size) {
    const float* score_act = (const float*)d_in[0];
    const float* score_bkg = (const float*)d_in[1];
    const float* feat_act  = (const float*)d_in[2];
    const float* feat_bkg  = (const float*)d_in[3];
    const float* label     = (const float*)d_in[4];
    const float* gt        = (const float*)d_in[5];
    const float* sup_cas   = (const float*)d_in[6];
    const float* cas_s     = (const float*)d_in[7];
    const float* cas_t     = (const float*)d_in[8];

    main_kernel<<<TOTAL_BLOCKS, 256>>>(feat_act, feat_bkg, gt, sup_cas, cas_s, cas_t);
    final_kernel<<<1, 256>>>(score_act, score_bkg, label, (float*)d_out);
}

// round 11
// speedup vs baseline: 1.2129x; 1.0202x over previous
#include <cuda_runtime.h>
#include <math.h>

#define BB 16
#define TT 2048
#define DD 2048
#define CC 100

#define ALPHA 0.0005f
#define MARGIN 100.0f
#define EPS_C 1e-7f

#define FEAT_DCHUNK 64                        // floats per d-strip
#define FEAT_NDCH (DD / FEAT_DCHUNK)          // 32
#define FEAT_BLOCKS (2 * BB * FEAT_NDCH)      // 1024
#define BTC_BLOCKS 512                        // 32 tchunks(64t) x 16 b
#define TOTAL_BLOCKS (FEAT_BLOCKS + BTC_BLOCKS)

// ---------------- scratch (device globals; zero-init at load) ----------------
// Invariant: zero at kernel_launch entry; final_kernel re-zeros after reading.
// g_res needs no zero-invariant: always fully written before read each launch.
__device__ float g_n2[2 * BB];          // squared norms of mean features (atomic-accum)
__device__ float g_sq[BB * CC];         // sum_t (sup - pmask)^2 per (b,c)
__device__ float g_pos[BB * CC];        // sum_t pmask per (b,c)
__device__ float g_st[1];               // sum (cas_s - cas_t)^2
__device__ float g_res[6];              // partials: cls, be, sup, cnt, um, st
__device__ unsigned int g_done;         // 2-block tail handshake

// ---------------- fused streaming kernel (R10-proven, untouched) -------------
__global__ __launch_bounds__(256) void main_kernel(
    const float* __restrict__ fa, const float* __restrict__ fb,
    const float* __restrict__ gt, const float* __restrict__ sup,
    const float* __restrict__ cas_s, const float* __restrict__ cas_t) {
    const int bz = blockIdx.x;
    const int tid = threadIdx.x;
    __shared__ float shbuf[16 * 16 * 4];   // feat: 16x16 float4; btc: 256 floats

    if (bz < FEAT_BLOCKS) {
        // ---- feat: block owns (tensor, b, 64-float d-strip) across ALL t ----
        const int dch = bz & (FEAT_NDCH - 1);
        const int z = bz >> 5;            // 0..31
        const int tensor = z >> 4;
        const int b = z & 15;
        const float* __restrict__ f = tensor ? fb : fa;

        const int lane16 = tid & 15;      // d-lane (float4)
        const int rg = tid >> 4;          // row-group 0..15
        const int d0 = dch * FEAT_DCHUNK + lane16 * 4;
        const float4* __restrict__ p =
            (const float4*)(f + (size_t)b * TT * DD + (size_t)rg * DD + d0);

        float4 acc = make_float4(0.f, 0.f, 0.f, 0.f);
#pragma unroll 8
        for (int t = 0; t < TT / 16; t++) {           // 128 iterations
            float4 v = __ldcs(p + (size_t)t * (16 * DD / 4));
            acc.x += v.x; acc.y += v.y; acc.z += v.z; acc.w += v.w;
        }

        // combine 16 row-group partials per d-column in shared
        float4* sh4 = (float4*)shbuf;     // [16 rg][16 lane]
        sh4[rg * 16 + lane16] = acc;
        __syncthreads();

        float partial = 0.f;
        if (tid < 16) {
            float4 c = sh4[tid];
#pragma unroll
            for (int r = 1; r < 16; r++) {
                float4 v = sh4[r * 16 + tid];
                c.x += v.x; c.y += v.y; c.z += v.z; c.w += v.w;
            }
            const float invT = 1.0f / TT;
            float x = c.x * invT, y = c.y * invT, zz = c.z * invT, w = c.w * invT;
            partial = x * x + y * y + zz * zz + w * w;
        }
        if (tid < 32) {
#pragma unroll
            for (int o = 16; o > 0; o >>= 1)
                partial += __shfl_xor_sync(0xFFFFFFFFu, partial, o);
            if (tid == 0) atomicAdd(&g_n2[z], partial);
        }
    } else {
        // ---- [B,T,C] streams: sup / pos / st ----
        const int i = bz - FEAT_BLOCKS;   // 0..511
        const int b = i >> 5;
        const int tci = i & 31;
        const int half = tid >> 7;        // 0 or 1
        const int c = tid & 127;
        const int t0 = tci * 64 + half * 32;

        float sq = 0.f, pos = 0.f, st = 0.f;
        if (c < CC) {
            size_t base = (size_t)b * TT * CC + (size_t)t0 * CC + c;
#pragma unroll 4
            for (int t = 0; t < 32; t++) {
                size_t o = base + (size_t)t * CC;
                float g = __ldcs(gt + o);
                float s = __ldcs(sup + o);
                float x = __ldcs(cas_s + o);
                float y = __ldcs(cas_t + o);
                float pm = (g > 0.5f) ? 1.f : 0.f;
                float d = s - pm;
                sq += d * d;
                pos += pm;
                float e = x - y;
                st += e * e;
            }
            atomicAdd(&g_sq[b * CC + c], sq);
            atomicAdd(&g_pos[b * CC + c], pos);
        }
        float* sh = shbuf;
        sh[tid] = st;
        __syncthreads();
        for (int s = 128; s > 0; s >>= 1) {
            if (tid < s) sh[tid] += sh[tid + s];
            __syncthreads();
        }
        if (tid == 0) atomicAdd(g_st, sh[0]);
    }
}

// ---------------- final: 2 concurrent blocks + tiny handshake ---------------
__device__ __forceinline__ float block_reduce_256(float v, float* red) {
    int tid = threadIdx.x;
    red[tid] = v;
    __syncthreads();
    for (int s = 128; s > 0; s >>= 1) {
        if (tid < s) red[tid] += red[tid + s];
        __syncthreads();
    }
    float r = red[0];
    __syncthreads();
    return r;
}

__global__ __launch_bounds__(256) void final_kernel(
    const float* __restrict__ score_act, const float* __restrict__ score_bkg,
    const float* __restrict__ label, float* __restrict__ out) {
    const int tid = threadIdx.x;
    __shared__ float red[256];
    __shared__ float lsum[BB];
    __shared__ unsigned int s_rank;

    if (blockIdx.x == 0) {
        // ---- BCE block: inputs only, no dependence on main's scratch ----
        if (tid < BB) lsum[tid] = 0.f;
        __syncthreads();
        for (int i = tid; i < BB * CC; i += 256)
            atomicAdd(&lsum[i / CC], label[i]);
        __syncthreads();

        float acc_cls = 0.f, acc_be = 0.f;
        const float tb = 1.0f / CC;
        for (int i = tid; i < BB * CC; i += 256) {
            float p = score_act[i];
            p = fminf(fmaxf(p, EPS_C), 1.0f - EPS_C);
            float t = label[i] / lsum[i / CC];
            acc_cls += t * logf(p) + (1.0f - t) * log1pf(-p);

            float q = score_bkg[i];
            q = fminf(fmaxf(q, EPS_C), 1.0f - EPS_C);
            acc_be += tb * logf(q) + (1.0f - tb) * log1pf(-q);
        }
        float sum_cls = block_reduce_256(acc_cls, red);
        float sum_be  = block_reduce_256(acc_be, red);
        if (tid == 0) {
            g_res[0] = sum_cls;
            g_res[1] = sum_be;
        }
    } else {
        // ---- scratch block: sup / cnt / um / st; zero scratch after read ----
        float acc_sup = 0.f, acc_cnt = 0.f;
        for (int i = tid; i < BB * CC; i += 256) {
            float pv = g_pos[i];
            float qv = g_sq[i];
            if (pv > 0.f) {
                acc_sup += sqrtf(qv);
                acc_cnt += 1.f;
            }
            g_pos[i] = 0.f;
            g_sq[i] = 0.f;
        }
        float sum_sup = block_reduce_256(acc_sup, red);
        float sum_cnt = block_reduce_256(acc_cnt, red);

        float um_part = 0.f;
        if (tid < BB) {
            float an = sqrtf(g_n2[tid]);
            float bn = sqrtf(g_n2[BB + tid]);
            float la = fmaxf(MARGIN - an, 0.f);
            float v = la + bn;
            um_part = v * v;
        }
        __syncthreads();
        if (tid < 2 * BB) g_n2[tid] = 0.f;
        float sum_um = block_reduce_256(um_part, red);

        if (tid == 0) {
            g_res[2] = sum_sup;
            g_res[3] = sum_cnt;
            g_res[4] = sum_um;
            g_res[5] = g_st[0];
            g_st[0] = 0.f;
        }
    }

    // ---- handshake: last of the 2 blocks assembles the output ----
    __threadfence();
    __syncthreads();
    if (tid == 0) s_rank = atomicAdd(&g_done, 1u);
    __syncthreads();
    if (s_rank != 1) return;

    if (tid == 0) {
        __threadfence();                 // acquire: other block's g_res writes
        g_done = 0;

        float loss_cls = -g_res[0] / (float)(BB * CC);
        float loss_be  = -g_res[1] / (float)(BB * CC);
        float loss_um  = g_res[4] / (float)BB;
        float loss_sup = g_res[2] / fmaxf(g_res[3], 1.0f);
        float loss_st  = g_res[5] / (float)(BB * TT * CC);

        float total = loss_cls + ALPHA * loss_um + loss_be + loss_sup + loss_st;
        out[0] = total;
        out[1] = loss_cls;
        out[2] = loss_be;
        out[3] = loss_um;
        out[4] = loss_sup;
        out[5] = loss_st;
    }
}

// ---------------- launch ----------------
extern "C" void kernel_launch(void* const* d_in, const int* in_sizes, int n_in,
                              void* d_out, int out_size) {
    const float* score_act = (const float*)d_in[0];
    const float* score_bkg = (const float*)d_in[1];
    const float* feat_act  = (const float*)d_in[2];
    const float* feat_bkg  = (const float*)d_in[3];
    const float* label     = (const float*)d_in[4];
    const float* gt        = (const float*)d_in[5];
    const float* sup_cas   = (const float*)d_in[6];
    const float* cas_s     = (const float*)d_in[7];
    const float* cas_t     = (const float*)d_in[8];

    main_kernel<<<TOTAL_BLOCKS, 256>>>(feat_act, feat_bkg, gt, sup_cas, cas_s, cas_t);
    final_kernel<<<2, 256>>>(score_act, score_bkg, label, (float*)d_out);
}

// round 12
// speedup vs baseline: 1.4203x; 1.1709x over previous
#include <cuda_runtime.h>
#include <math.h>

#define BB 16
#define TT 2048
#define DD 2048
#define CC 100

#define ALPHA 0.0005f
#define MARGIN 100.0f
#define EPS_C 1e-7f

#define FEAT_DCHUNK 64                        // floats per d-strip
#define FEAT_NDCH (DD / FEAT_DCHUNK)          // 32
#define FEAT_BLOCKS (2 * BB * FEAT_NDCH)      // 1024
#define BTC_BLOCKS 512                        // 32 tchunks(64t) x 16 b
#define TOTAL_BLOCKS (1 + FEAT_BLOCKS + BTC_BLOCKS)

// ---------------- scratch (device globals; zero-init at load) ----------------
// Invariant: zero at kernel_launch entry; final_kernel re-zeros after reading.
// g_res needs no zero-invariant: fully written each launch before being read.
__device__ float g_n2[2 * BB];          // squared norms of mean features (atomic-accum)
__device__ float g_sq[BB * CC];         // sum_t (sup - pmask)^2 per (b,c)
__device__ float g_pos[BB * CC];        // sum_t pmask per (b,c)
__device__ float g_st[1];               // sum (cas_s - cas_t)^2
__device__ float g_res[2];              // BCE partials: cls, be (written by main)

// ---------------- fused streaming kernel + concurrent BCE block --------------
__global__ __launch_bounds__(256) void main_kernel(
    const float* __restrict__ fa, const float* __restrict__ fb,
    const float* __restrict__ gt, const float* __restrict__ sup,
    const float* __restrict__ cas_s, const float* __restrict__ cas_t,
    const float* __restrict__ score_act, const float* __restrict__ score_bkg,
    const float* __restrict__ label) {
    const int bz = blockIdx.x;
    const int tid = threadIdx.x;
    __shared__ float shbuf[16 * 16 * 4];   // feat: 16x16 float4; others: floats

    if (bz == 0) {
        // ---- BCE block: input-only, overlaps the big stream ----
        __shared__ float lsum[BB];
        if (tid < BB) lsum[tid] = 0.f;
        __syncthreads();
        for (int i = tid; i < BB * CC; i += 256)
            atomicAdd(&lsum[i / CC], label[i]);
        __syncthreads();

        float acc_cls = 0.f, acc_be = 0.f;
        const float tb = 1.0f / CC;
        for (int i = tid; i < BB * CC; i += 256) {
            float p = score_act[i];
            p = fminf(fmaxf(p, EPS_C), 1.0f - EPS_C);
            float t = label[i] / lsum[i / CC];
            acc_cls += t * logf(p) + (1.0f - t) * log1pf(-p);

            float q = score_bkg[i];
            q = fminf(fmaxf(q, EPS_C), 1.0f - EPS_C);
            acc_be += tb * logf(q) + (1.0f - tb) * log1pf(-q);
        }
        float* sh = shbuf;
        sh[tid] = acc_cls;
        sh[256 + tid] = acc_be;
        __syncthreads();
        for (int s = 128; s > 0; s >>= 1) {
            if (tid < s) {
                sh[tid] += sh[tid + s];
                sh[256 + tid] += sh[256 + tid + s];
            }
            __syncthreads();
        }
        if (tid == 0) {
            g_res[0] = sh[0];
            g_res[1] = sh[256];
        }
    } else if (bz <= FEAT_BLOCKS) {
        // ---- feat: block owns (tensor, b, 64-float d-strip) across ALL t ----
        const int fz = bz - 1;
        const int dch = fz & (FEAT_NDCH - 1);
        const int z = fz >> 5;            // 0..31
        const int tensor = z >> 4;
        const int b = z & 15;
        const float* __restrict__ f = tensor ? fb : fa;

        const int lane16 = tid & 15;      // d-lane (float4)
        const int rg = tid >> 4;          // row-group 0..15
        const int d0 = dch * FEAT_DCHUNK + lane16 * 4;
        const float4* __restrict__ p =
            (const float4*)(f + (size_t)b * TT * DD + (size_t)rg * DD + d0);

        float4 acc = make_float4(0.f, 0.f, 0.f, 0.f);
#pragma unroll 8
        for (int t = 0; t < TT / 16; t++) {           // 128 iterations
            float4 v = __ldcs(p + (size_t)t * (16 * DD / 4));
            acc.x += v.x; acc.y += v.y; acc.z += v.z; acc.w += v.w;
        }

        // combine 16 row-group partials per d-column in shared
        float4* sh4 = (float4*)shbuf;     // [16 rg][16 lane]
        sh4[rg * 16 + lane16] = acc;
        __syncthreads();

        float partial = 0.f;
        if (tid < 16) {
            float4 c = sh4[tid];
#pragma unroll
            for (int r = 1; r < 16; r++) {
                float4 v = sh4[r * 16 + tid];
                c.x += v.x; c.y += v.y; c.z += v.z; c.w += v.w;
            }
            const float invT = 1.0f / TT;
            float x = c.x * invT, y = c.y * invT, zz = c.z * invT, w = c.w * invT;
            partial = x * x + y * y + zz * zz + w * w;
        }
        if (tid < 32) {
#pragma unroll
            for (int o = 16; o > 0; o >>= 1)
                partial += __shfl_xor_sync(0xFFFFFFFFu, partial, o);
            if (tid == 0) atomicAdd(&g_n2[z], partial);
        }
    } else {
        // ---- [B,T,C] streams: sup / pos / st ----
        const int i = bz - 1 - FEAT_BLOCKS;   // 0..511
        const int b = i >> 5;
        const int tci = i & 31;
        const int half = tid >> 7;        // 0 or 1
        const int c = tid & 127;
        const int t0 = tci * 64 + half * 32;

        float sq = 0.f, pos = 0.f, st = 0.f;
        if (c < CC) {
            size_t base = (size_t)b * TT * CC + (size_t)t0 * CC + c;
#pragma unroll 4
            for (int t = 0; t < 32; t++) {
                size_t o = base + (size_t)t * CC;
                float g = __ldcs(gt + o);
                float s = __ldcs(sup + o);
                float x = __ldcs(cas_s + o);
                float y = __ldcs(cas_t + o);
                float pm = (g > 0.5f) ? 1.f : 0.f;
                float d = s - pm;
                sq += d * d;
                pos += pm;
                float e = x - y;
                st += e * e;
            }
            atomicAdd(&g_sq[b * CC + c], sq);
            atomicAdd(&g_pos[b * CC + c], pos);
        }
        float* sh = shbuf;
        sh[tid] = st;
        __syncthreads();
        for (int s = 128; s > 0; s >>= 1) {
            if (tid < s) sh[tid] += sh[tid + s];
            __syncthreads();
        }
        if (tid == 0) atomicAdd(g_st, sh[0]);
    }
}

// ---------------- final: one block, scratch-only (L2-hot) -------------------
__device__ __forceinline__ float block_reduce_256(float v, float* red) {
    int tid = threadIdx.x;
    red[tid] = v;
    __syncthreads();
    for (int s = 128; s > 0; s >>= 1) {
        if (tid < s) red[tid] += red[tid + s];
        __syncthreads();
    }
    float r = red[0];
    __syncthreads();
    return r;
}

__global__ __launch_bounds__(256) void final_kernel(float* __restrict__ out) {
    const int tid = threadIdx.x;
    __shared__ float red[256];

    // ---- loss_sup; zero g_sq/g_pos after reading ----
    float acc_sup = 0.f, acc_cnt = 0.f;
    for (int i = tid; i < BB * CC; i += 256) {
        float pv = g_pos[i];
        float qv = g_sq[i];
        if (pv > 0.f) {
            acc_sup += sqrtf(qv);
            acc_cnt += 1.f;
        }
        g_pos[i] = 0.f;
        g_sq[i] = 0.f;
    }
    float sum_sup = block_reduce_256(acc_sup, red);
    float sum_cnt = block_reduce_256(acc_cnt, red);

    // ---- loss_um from g_n2 (16 lanes active); zero g_n2 after read ----
    float um_part = 0.f;
    if (tid < BB) {
        float an = sqrtf(g_n2[tid]);
        float bn = sqrtf(g_n2[BB + tid]);
        float la = fmaxf(MARGIN - an, 0.f);
        float v = la + bn;
        um_part = v * v;
    }
    __syncthreads();
    if (tid < 2 * BB) g_n2[tid] = 0.f;
    float sum_um = block_reduce_256(um_part, red);

    if (tid == 0) {
        float st_sum = g_st[0];
        g_st[0] = 0.f;

        float loss_cls = -g_res[0] / (float)(BB * CC);
        float loss_be  = -g_res[1] / (float)(BB * CC);
        float loss_um  = sum_um / (float)BB;
        float loss_sup = sum_sup / fmaxf(sum_cnt, 1.0f);
        float loss_st  = st_sum / (float)(BB * TT * CC);

        float total = loss_cls + ALPHA * loss_um + loss_be + loss_sup + loss_st;
        out[0] = total;
        out[1] = loss_cls;
        out[2] = loss_be;
        out[3] = loss_um;
        out[4] = loss_sup;
        out[5] = loss_st;
    }
}

// ---------------- launch ----------------
extern "C" void kernel_launch(void* const* d_in, const int* in_sizes, int n_in,
                              void* d_out, int out_size) {
    const float* score_act = (const float*)d_in[0];
    const float* score_bkg = (const float*)d_in[1];
    const float* feat_act  = (const float*)d_in[2];
    const float* feat_bkg  = (const float*)d_in[3];
    const float* label     = (const float*)d_in[4];
    const float* gt        = (const float*)d_in[5];
    const float* sup_cas   = (const float*)d_in[6];
    const float* cas_s     = (const float*)d_in[7];
    const float* cas_t     = (const float*)d_in[8];

    main_kernel<<<TOTAL_BLOCKS, 256>>>(
        feat_act, feat_bkg, gt, sup_cas, cas_s, cas_t,
        score_act, score_bkg, label);
    final_kernel<<<1, 256>>>((float*)d_out);
}

// round 16
// speedup vs baseline: 1.4437x; 1.0165x over previous
#include <cuda_runtime.h>
#include <math.h>

#define BB 16
#define TT 2048
#define DD 2048
#define CC 100

#define ALPHA 0.0005f
#define MARGIN 100.0f
#define EPS_C 1e-7f

#define FEAT_DCHUNK 64                        // floats per d-strip
#define FEAT_NDCH (DD / FEAT_DCHUNK)          // 32
#define FEAT_BLOCKS (2 * BB * FEAT_NDCH)      // 1024
#define BTC_BLOCKS 512                        // 32 tchunks(64t) x 16 b
#define TOTAL_BLOCKS (1 + FEAT_BLOCKS + BTC_BLOCKS)

// ---------------- scratch (device globals; zero-init at load) ----------------
// Invariant: zero at kernel_launch entry; final_kernel re-zeros after reading.
// g_res needs no zero-invariant: fully written each launch before being read.
__device__ float g_n2[2 * BB];          // squared norms of mean features (atomic-accum)
__device__ float g_sq[BB * CC];         // sum_t (sup - pmask)^2 per (b,c)
__device__ float g_pos[BB * CC];        // sum_t pmask per (b,c)
__device__ float g_st[1];               // sum (cas_s - cas_t)^2
__device__ float g_res[2];              // BCE partials: cls, be (written by main)

// ---------------- fused streaming kernel + concurrent BCE block --------------
// min-blocks 8 caps regs at 32: spills (if any) land only in the BCE branch,
// which is 1 block of 1537 and fully hidden under the 565 MB stream.
__global__ __launch_bounds__(256, 8) void main_kernel(
    const float* __restrict__ fa, const float* __restrict__ fb,
    const float* __restrict__ gt, const float* __restrict__ sup,
    const float* __restrict__ cas_s, const float* __restrict__ cas_t,
    const float* __restrict__ score_act, const float* __restrict__ score_bkg,
    const float* __restrict__ label) {
    const int bz = blockIdx.x;
    const int tid = threadIdx.x;
    __shared__ float shbuf[16 * 16 * 4];   // feat: 16x16 float4; others: floats

    if (bz == 0) {
        // ---- BCE block: input-only, overlaps the big stream ----
        __shared__ float lsum[BB];
        if (tid < BB) lsum[tid] = 0.f;
        __syncthreads();
        for (int i = tid; i < BB * CC; i += 256)
            atomicAdd(&lsum[i / CC], label[i]);
        __syncthreads();

        float acc_cls = 0.f, acc_be = 0.f;
        const float tb = 1.0f / CC;
        for (int i = tid; i < BB * CC; i += 256) {
            float p = score_act[i];
            p = fminf(fmaxf(p, EPS_C), 1.0f - EPS_C);
            float t = label[i] / lsum[i / CC];
            acc_cls += t * logf(p) + (1.0f - t) * log1pf(-p);

            float q = score_bkg[i];
            q = fminf(fmaxf(q, EPS_C), 1.0f - EPS_C);
            acc_be += tb * logf(q) + (1.0f - tb) * log1pf(-q);
        }
        float* sh = shbuf;
        sh[tid] = acc_cls;
        sh[256 + tid] = acc_be;
        __syncthreads();
        for (int s = 128; s > 0; s >>= 1) {
            if (tid < s) {
                sh[tid] += sh[tid + s];
                sh[256 + tid] += sh[256 + tid + s];
            }
            __syncthreads();
        }
        if (tid == 0) {
            g_res[0] = sh[0];
            g_res[1] = sh[256];
        }
    } else if (bz <= FEAT_BLOCKS) {
        // ---- feat: block owns (tensor, b, 64-float d-strip) across ALL t ----
        const int fz = bz - 1;
        const int dch = fz & (FEAT_NDCH - 1);
        const int z = fz >> 5;            // 0..31
        const int tensor = z >> 4;
        const int b = z & 15;
        const float* __restrict__ f = tensor ? fb : fa;

        const int lane16 = tid & 15;      // d-lane (float4)
        const int rg = tid >> 4;          // row-group 0..15
        const int d0 = dch * FEAT_DCHUNK + lane16 * 4;
        const float4* __restrict__ p =
            (const float4*)(f + (size_t)b * TT * DD + (size_t)rg * DD + d0);

        float4 acc = make_float4(0.f, 0.f, 0.f, 0.f);
#pragma unroll 16
        for (int t = 0; t < TT / 16; t++) {           // 128 iterations
            float4 v = __ldcs(p + (size_t)t * (16 * DD / 4));
            acc.x += v.x; acc.y += v.y; acc.z += v.z; acc.w += v.w;
        }

        // combine 16 row-group partials per d-column in shared
        float4* sh4 = (float4*)shbuf;     // [16 rg][16 lane]
        sh4[rg * 16 + lane16] = acc;
        __syncthreads();

        float partial = 0.f;
        if (tid < 16) {
            float4 c = sh4[tid];
#pragma unroll
            for (int r = 1; r < 16; r++) {
                float4 v = sh4[r * 16 + tid];
                c.x += v.x; c.y += v.y; c.z += v.z; c.w += v.w;
            }
            const float invT = 1.0f / TT;
            float x = c.x * invT, y = c.y * invT, zz = c.z * invT, w = c.w * invT;
            partial = x * x + y * y + zz * zz + w * w;
        }
        if (tid < 32) {
#pragma unroll
            for (int o = 16; o > 0; o >>= 1)
                partial += __shfl_xor_sync(0xFFFFFFFFu, partial, o);
            if (tid == 0) atomicAdd(&g_n2[z], partial);
        }
    } else {
        // ---- [B,T,C] streams: sup / pos / st ----
        const int i = bz - 1 - FEAT_BLOCKS;   // 0..511
        const int b = i >> 5;
        const int tci = i & 31;
        const int half = tid >> 7;        // 0 or 1
        const int c = tid & 127;
        const int t0 = tci * 64 + half * 32;

        float sq = 0.f, pos = 0.f, st = 0.f;
        if (c < CC) {
            size_t base = (size_t)b * TT * CC + (size_t)t0 * CC + c;
#pragma unroll 4
            for (int t = 0; t < 32; t++) {
                size_t o = base + (size_t)t * CC;
                float g = __ldcs(gt + o);
                float s = __ldcs(sup + o);
                float x = __ldcs(cas_s + o);
                float y = __ldcs(cas_t + o);
                float pm = (g > 0.5f) ? 1.f : 0.f;
                float d = s - pm;
                sq += d * d;
                pos += pm;
                float e = x - y;
                st += e * e;
            }
            atomicAdd(&g_sq[b * CC + c], sq);
            atomicAdd(&g_pos[b * CC + c], pos);
        }
        float* sh = shbuf;
        sh[tid] = st;
        __syncthreads();
        for (int s = 128; s > 0; s >>= 1) {
            if (tid < s) sh[tid] += sh[tid + s];
            __syncthreads();
        }
        if (tid == 0) atomicAdd(g_st, sh[0]);
    }
}

// ---------------- final: one block, scratch-only (L2-hot) -------------------
__device__ __forceinline__ float block_reduce_256(float v, float* red) {
    int tid = threadIdx.x;
    red[tid] = v;
    __syncthreads();
    for (int s = 128; s > 0; s >>= 1) {
        if (tid < s) red[tid] += red[tid + s];
        __syncthreads();
    }
    float r = red[0];
    __syncthreads();
    return r;
}

__global__ __launch_bounds__(256) void final_kernel(float* __restrict__ out) {
    const int tid = threadIdx.x;
    __shared__ float red[256];

    // ---- loss_sup; zero g_sq/g_pos after reading ----
    float acc_sup = 0.f, acc_cnt = 0.f;
    for (int i = tid; i < BB * CC; i += 256) {
        float pv = g_pos[i];
        float qv = g_sq[i];
        if (pv > 0.f) {
            acc_sup += sqrtf(qv);
            acc_cnt += 1.f;
        }
        g_pos[i] = 0.f;
        g_sq[i] = 0.f;
    }
    float sum_sup = block_reduce_256(acc_sup, red);
    float sum_cnt = block_reduce_256(acc_cnt, red);

    // ---- loss_um from g_n2 (16 lanes active); zero g_n2 after read ----
    float um_part = 0.f;
    if (tid < BB) {
        float an = sqrtf(g_n2[tid]);
        float bn = sqrtf(g_n2[BB + tid]);
        float la = fmaxf(MARGIN - an, 0.f);
        float v = la + bn;
        um_part = v * v;
    }
    __syncthreads();
    if (tid < 2 * BB) g_n2[tid] = 0.f;
    float sum_um = block_reduce_256(um_part, red);

    if (tid == 0) {
        float st_sum = g_st[0];
        g_st[0] = 0.f;

        float loss_cls = -g_res[0] / (float)(BB * CC);
        float loss_be  = -g_res[1] / (float)(BB * CC);
        float loss_um  = sum_um / (float)BB;
        float loss_sup = sum_sup / fmaxf(sum_cnt, 1.0f);
        float loss_st  = st_sum / (float)(BB * TT * CC);

        float total = loss_cls + ALPHA * loss_um + loss_be + loss_sup + loss_st;
        out[0] = total;
        out[1] = loss_cls;
        out[2] = loss_be;
        out[3] = loss_um;
        out[4] = loss_sup;
        out[5] = loss_st;
    }
}

// ---------------- launch ----------------
extern "C" void kernel_launch(void* const* d_in, const int* in_sizes, int n_in,
                              void* d_out, int out_size) {
    const float* score_act = (const float*)d_in[0];
    const float* score_bkg = (const float*)d_in[1];
    const float* feat_act  = (const float*)d_in[2];
    const float* feat_bkg  = (const float*)d_in[3];
    const float* label     = (const float*)d_in[4];
    const float* gt        = (const float*)d_in[5];
    const float* sup_cas   = (const float*)d_in[6];
    const float* cas_s     = (const float*)d_in[7];
    const float* cas_t     = (const float*)d_in[8];

    main_kernel<<<TOTAL_BLOCKS, 256>>>(
        feat_act, feat_bkg, gt, sup_cas, cas_s, cas_t,
        score_act, score_bkg, label);
    final_kernel<<<1, 256>>>((float*)d_out);
}